// round 7
// baseline (speedup 1.0000x reference)
#include <cuda_runtime.h>
#include <math.h>
#include <stdint.h>

// Problem constants
#define NB    2
#define TSEQ  2048
#define CDIM  2048
#define NH    16
#define NKV   4
#define HD    128
#define MROWS (NB * TSEQ)          // 4096
#define KVW   (2 * NKV * HD)       // 1024

// Scratch (no cudaMalloc allowed)
__device__ float g_Q[(size_t)MROWS * CDIM];
__device__ float g_KV[(size_t)MROWS * KVW];
__device__ float g_Y[(size_t)MROWS * CDIM];
// pre-rounded (tf32) copies of inputs
__device__ float g_X[(size_t)MROWS * CDIM];
__device__ float g_Wq[(size_t)CDIM * CDIM];
__device__ float g_Wkv[(size_t)KVW * CDIM];
__device__ float g_Wo[(size_t)CDIM * CDIM];

// ---------------------------------------------------------------------------
// Helpers
// ---------------------------------------------------------------------------
__device__ __forceinline__ uint32_t f2tf32(float x) {
    uint32_t r;
    asm("cvt.rna.tf32.f32 %0, %1;\n" : "=r"(r) : "f"(x));
    return r;
}
__device__ __forceinline__ float rtf(float x) { return __uint_as_float(f2tf32(x)); }

__device__ __forceinline__ void mma_tf32(float* c,
                                         uint32_t a0, uint32_t a1, uint32_t a2, uint32_t a3,
                                         uint32_t b0, uint32_t b1) {
    asm("mma.sync.aligned.m16n8k8.row.col.f32.tf32.tf32.f32 "
        "{%0,%1,%2,%3}, {%4,%5,%6,%7}, {%8,%9}, {%0,%1,%2,%3};\n"
        : "+f"(c[0]), "+f"(c[1]), "+f"(c[2]), "+f"(c[3])
        : "r"(a0), "r"(a1), "r"(a2), "r"(a3), "r"(b0), "r"(b1));
}

__device__ __forceinline__ void cp_async16(uint32_t smem_addr, const float* gptr) {
    asm volatile("cp.async.cg.shared.global [%0], [%1], 16;\n"
                 :: "r"(smem_addr), "l"(gptr));
}

// ---------------------------------------------------------------------------
// Pre-round fp32 -> tf32 (vectorized elementwise)
// ---------------------------------------------------------------------------
__global__ void round_tf32_kernel(const float* __restrict__ in, float* __restrict__ out, int n4)
{
    int i = blockIdx.x * blockDim.x + threadIdx.x;
    if (i >= n4) return;
    float4 v = ((const float4*)in)[i];
    v.x = rtf(v.x); v.y = rtf(v.y); v.z = rtf(v.z); v.w = rtf(v.w);
    ((float4*)out)[i] = v;
}

// ---------------------------------------------------------------------------
// TF32 tensor-core NT GEMM: C[M,N] = A[M,K] * B[N,K]^T  (row-major, row dots)
// Inputs MUST be pre-rounded tf32 (raw bits to mma). Permuted-k fragment
// mapping: mma-col tig <- logical 2*tig, mma-col tig+4 <- logical 2*tig+1,
// identical for A and B (dot invariant) -> float2 fragment loads (LDS.64).
// PADK=40 (==8 mod 32): conflict-free .64 per half-warp.
// 128x128 tile, BK=32, 256 threads (8 warps 2x4), warp tile 64x32.
// roundOut!=0: round C to tf32 on store (for tensors consumed by later mma).
// ---------------------------------------------------------------------------
#define BKG   32
#define PADK  40
#define TILEF (128 * PADK)

__global__ __launch_bounds__(256, 2) void gemm_tf32_nt(
    const float* __restrict__ A, const float* __restrict__ B,
    float* __restrict__ C, int M, int N, int K, int roundOut)
{
    extern __shared__ float sm[];
    float* Abuf[2] = { sm,             sm + TILEF };
    float* Bbuf[2] = { sm + 2*TILEF,   sm + 3*TILEF };

    const int tid  = threadIdx.x;
    const int bm   = blockIdx.y * 128;
    const int bn   = blockIdx.x * 128;
    const int warp = tid >> 5;
    const int lane = tid & 31;
    const int wm   = warp >> 2;
    const int wn   = warp & 3;
    const int gid  = lane >> 2;
    const int tig  = lane & 3;

    const int crow  = tid >> 1;
    const int cquad = tid & 1;
    const float* gA = A + (size_t)(bm + crow) * K + cquad * 16;
    const float* gB = B + (size_t)(bn + crow) * K + cquad * 16;
    const int soff  = crow * PADK + cquad * 16;

    float acc[4][4][4];
#pragma unroll
    for (int mt = 0; mt < 4; mt++)
#pragma unroll
        for (int nt = 0; nt < 4; nt++)
#pragma unroll
            for (int i = 0; i < 4; i++) acc[mt][nt][i] = 0.f;

    const int niter = K / BKG;

    {
        uint32_t sa = (uint32_t)__cvta_generic_to_shared(Abuf[0] + soff);
        uint32_t sb = (uint32_t)__cvta_generic_to_shared(Bbuf[0] + soff);
#pragma unroll
        for (int i = 0; i < 4; i++) {
            cp_async16(sa + i * 16, gA + i * 4);
            cp_async16(sb + i * 16, gB + i * 4);
        }
        asm volatile("cp.async.commit_group;\n" ::: "memory");
    }

    for (int k0 = 0; k0 < niter; k0++) {
        const int buf = k0 & 1;
        if (k0 + 1 < niter) {
            const int koff = (k0 + 1) * BKG;
            uint32_t sa = (uint32_t)__cvta_generic_to_shared(Abuf[buf ^ 1] + soff);
            uint32_t sb = (uint32_t)__cvta_generic_to_shared(Bbuf[buf ^ 1] + soff);
#pragma unroll
            for (int i = 0; i < 4; i++) {
                cp_async16(sa + i * 16, gA + koff + i * 4);
                cp_async16(sb + i * 16, gB + koff + i * 4);
            }
        }
        asm volatile("cp.async.commit_group;\n" ::: "memory");
        asm volatile("cp.async.wait_group 1;\n" ::: "memory");
        __syncthreads();

        const float2* As2 = (const float2*)Abuf[buf];
        const float2* Bs2 = (const float2*)Bbuf[buf];
#pragma unroll
        for (int ks = 0; ks < 4; ks++) {
            const int kc = ks * 8;
            uint32_t af[4][4], bf[4][2];
#pragma unroll
            for (int mt = 0; mt < 4; mt++) {
                const int r = wm * 64 + mt * 16 + gid;
                float2 lo = As2[(r * PADK + kc) / 2 + tig];
                float2 hi = As2[((r + 8) * PADK + kc) / 2 + tig];
                af[mt][0] = __float_as_uint(lo.x);
                af[mt][2] = __float_as_uint(lo.y);
                af[mt][1] = __float_as_uint(hi.x);
                af[mt][3] = __float_as_uint(hi.y);
            }
#pragma unroll
            for (int nt = 0; nt < 4; nt++) {
                const int r = wn * 32 + nt * 8 + gid;
                float2 v = Bs2[(r * PADK + kc) / 2 + tig];
                bf[nt][0] = __float_as_uint(v.x);
                bf[nt][1] = __float_as_uint(v.y);
            }
#pragma unroll
            for (int mt = 0; mt < 4; mt++)
#pragma unroll
                for (int nt = 0; nt < 4; nt++)
                    mma_tf32(acc[mt][nt], af[mt][0], af[mt][1], af[mt][2], af[mt][3],
                             bf[nt][0], bf[nt][1]);
        }
        __syncthreads();
    }

    // NOTE: output cols of each mma are (tig*2, tig*2+1) as before (output
    // layout is unaffected by the k-permutation).
#pragma unroll
    for (int mt = 0; mt < 4; mt++) {
        const int r0 = bm + wm * 64 + mt * 16 + gid;
#pragma unroll
        for (int nt = 0; nt < 4; nt++) {
            const int c0 = bn + wn * 32 + nt * 8 + tig * 2;
            float o0 = acc[mt][nt][0], o1 = acc[mt][nt][1];
            float o2 = acc[mt][nt][2], o3 = acc[mt][nt][3];
            if (roundOut) { o0 = rtf(o0); o1 = rtf(o1); o2 = rtf(o2); o3 = rtf(o3); }
            *(float2*)&C[(size_t)r0 * N + c0]       = make_float2(o0, o1);
            *(float2*)&C[(size_t)(r0 + 8) * N + c0] = make_float2(o2, o3);
        }
    }
}

// ---------------------------------------------------------------------------
// RoPE: in-place, layout [rows, nheads, 128], given row stride (floats).
// Writes tf32-rounded outputs (consumed raw by the attention mma).
// ---------------------------------------------------------------------------
__global__ void rope_kernel(float* __restrict__ X, int rows, int nheads, int rowstride)
{
    int idx = blockIdx.x * blockDim.x + threadIdx.x;
    int total = rows * nheads * 64;
    if (idx >= total) return;
    int i   = idx & 63;
    int h   = (idx >> 6) % nheads;
    int row = idx / (64 * nheads);
    int t   = row & (TSEQ - 1);

    float freq = expf(-(float)i * (9.210340371976184f / 64.0f));
    float ang = (float)t * freq;
    float s, c;
    sincosf(ang, &s, &c);

    float* p = X + (size_t)row * rowstride + h * 128;
    float x0 = p[i];
    float x1 = p[i + 64];
    p[i]      = rtf(x0 * c - x1 * s);
    p[i + 64] = rtf(x1 * c + x0 * s);
}

// ---------------------------------------------------------------------------
// Tensor-core causal flash attention (tf32 mma.sync, fp32 softmax).
// K (rope-rounded) and V (KV-GEMM-rounded) are already tf32 -> raw-bit frags.
// Permuted-k mapping as in the GEMM (consistent for QK and PV pairs).
// KPAD=136 (.64 conflict-free), VPAD=132 (strided .32 conflict-free under
// 2*tig row mapping), PPAD=40.
// ---------------------------------------------------------------------------
#define KPAD  136
#define VPAD  132
#define PPAD  40
#define KTILE (32 * KPAD)
#define VTILE (32 * VPAD)
#define BUFSZ (KTILE + VTILE)
#define ATTN_SMEM ((2 * BUFSZ + 64 * PPAD) * 4)   // 78848 bytes

__global__ __launch_bounds__(128, 2) void attn_mma_kernel(
    const float* __restrict__ Q, const float* __restrict__ KV,
    float* __restrict__ Y)
{
    extern __shared__ float sm[];
    float* Ps = sm + 2 * BUFSZ;

    const int b   = blockIdx.z;
    const int h   = blockIdx.y;
    const int q0  = blockIdx.x * 64;
    const int kvh = h >> 2;
    const int tid  = threadIdx.x;
    const int warp = tid >> 5;
    const int lane = tid & 31;
    const int gid  = lane >> 2;
    const int tig  = lane & 3;

    const float scale = 0.08838834764831845f;   // 1/sqrt(128)

    // Q fragments with permuted-k mapping: a0/a2 <- logical cols 2tig, 2tig+1
    uint32_t qf[16][4];
    {
        const float* qp  = Q + (size_t)(b * TSEQ + q0 + warp * 16 + gid) * CDIM + h * 128;
        const float* qp8 = qp + 8 * CDIM;
#pragma unroll
        for (int ks = 0; ks < 16; ks++) {
            qf[ks][0] = f2tf32(qp [ks * 8 + 2 * tig]     * scale);
            qf[ks][2] = f2tf32(qp [ks * 8 + 2 * tig + 1] * scale);
            qf[ks][1] = f2tf32(qp8[ks * 8 + 2 * tig]     * scale);
            qf[ks][3] = f2tf32(qp8[ks * 8 + 2 * tig + 1] * scale);
        }
    }

    float o[16][4];
#pragma unroll
    for (int nt = 0; nt < 16; nt++)
#pragma unroll
        for (int i = 0; i < 4; i++) o[nt][i] = 0.f;
    float m0 = -1e30f, m1 = -1e30f, l0 = 0.f, l1 = 0.f;

    const int nkt = q0 / 32 + 2;

    {
        float* Kb = sm;
        float* Vb = sm + KTILE;
#pragma unroll
        for (int i = 0; i < 8; i++) {
            int idx = tid + i * 128;
            int r = idx >> 5, c4 = idx & 31;
            const float* src = KV + (size_t)(b * TSEQ + r) * KVW + kvh * 128 + c4 * 4;
            cp_async16((uint32_t)__cvta_generic_to_shared(Kb + r * KPAD + c4 * 4), src);
            cp_async16((uint32_t)__cvta_generic_to_shared(Vb + r * VPAD + c4 * 4), src + NKV * HD);
        }
        asm volatile("cp.async.commit_group;\n" ::: "memory");
    }

    const int row0 = warp * 16 + gid;

    for (int t = 0; t < nkt; t++) {
        const int buf = t & 1;
        if (t + 1 < nkt) {
            const int s1 = (t + 1) * 32;
            float* Kb = sm + (buf ^ 1) * BUFSZ;
            float* Vb = Kb + KTILE;
#pragma unroll
            for (int i = 0; i < 8; i++) {
                int idx = tid + i * 128;
                int r = idx >> 5, c4 = idx & 31;
                const float* src = KV + (size_t)(b * TSEQ + s1 + r) * KVW + kvh * 128 + c4 * 4;
                cp_async16((uint32_t)__cvta_generic_to_shared(Kb + r * KPAD + c4 * 4), src);
                cp_async16((uint32_t)__cvta_generic_to_shared(Vb + r * VPAD + c4 * 4), src + NKV * HD);
            }
        }
        asm volatile("cp.async.commit_group;\n" ::: "memory");
        asm volatile("cp.async.wait_group 1;\n" ::: "memory");
        __syncthreads();

        const float* Kb = sm + buf * BUFSZ;
        const float* Vb = Kb + KTILE;
        const int s0 = t * 32;

        float s[4][4];
#pragma unroll
        for (int nt = 0; nt < 4; nt++)
#pragma unroll
            for (int i = 0; i < 4; i++) s[nt][i] = 0.f;

        // S = Q K^T : K frags via LDS.64, raw bits (K already tf32)
#pragma unroll
        for (int ks = 0; ks < 16; ks++) {
            const int kc = ks * 8;
#pragma unroll
            for (int nt = 0; nt < 4; nt++) {
                float2 kv2 = *(const float2*)&Kb[(nt * 8 + gid) * KPAD + kc + 2 * tig];
                mma_tf32(s[nt], qf[ks][0], qf[ks][1], qf[ks][2], qf[ks][3],
                         __float_as_uint(kv2.x), __float_as_uint(kv2.y));
            }
        }

        if (t >= nkt - 2) {
            const int r0g = q0 + row0;
#pragma unroll
            for (int nt = 0; nt < 4; nt++) {
                const int c = s0 + nt * 8 + tig * 2;
                if (c > r0g)         s[nt][0] = -1e30f;
                if (c + 1 > r0g)     s[nt][1] = -1e30f;
                if (c > r0g + 8)     s[nt][2] = -1e30f;
                if (c + 1 > r0g + 8) s[nt][3] = -1e30f;
            }
        }

        float rm0 = s[0][0], rm1 = s[0][2];
#pragma unroll
        for (int nt = 0; nt < 4; nt++) {
            rm0 = fmaxf(rm0, fmaxf(s[nt][0], s[nt][1]));
            rm1 = fmaxf(rm1, fmaxf(s[nt][2], s[nt][3]));
        }
        rm0 = fmaxf(rm0, __shfl_xor_sync(0xffffffffu, rm0, 1));
        rm0 = fmaxf(rm0, __shfl_xor_sync(0xffffffffu, rm0, 2));
        rm1 = fmaxf(rm1, __shfl_xor_sync(0xffffffffu, rm1, 1));
        rm1 = fmaxf(rm1, __shfl_xor_sync(0xffffffffu, rm1, 2));

        float mt0 = fmaxf(m0, rm0), mt1 = fmaxf(m1, rm1);
        float c0 = __expf(m0 - mt0), c1 = __expf(m1 - mt1);
        m0 = mt0; m1 = mt1;

        float rs0 = 0.f, rs1 = 0.f;
#pragma unroll
        for (int nt = 0; nt < 4; nt++) {
            s[nt][0] = __expf(s[nt][0] - m0); rs0 += s[nt][0];
            s[nt][1] = __expf(s[nt][1] - m0); rs0 += s[nt][1];
            s[nt][2] = __expf(s[nt][2] - m1); rs1 += s[nt][2];
            s[nt][3] = __expf(s[nt][3] - m1); rs1 += s[nt][3];
        }
        rs0 += __shfl_xor_sync(0xffffffffu, rs0, 1);
        rs0 += __shfl_xor_sync(0xffffffffu, rs0, 2);
        rs1 += __shfl_xor_sync(0xffffffffu, rs1, 1);
        rs1 += __shfl_xor_sync(0xffffffffu, rs1, 2);
        l0 = l0 * c0 + rs0;
        l1 = l1 * c1 + rs1;

#pragma unroll
        for (int nt = 0; nt < 16; nt++) {
            o[nt][0] *= c0; o[nt][1] *= c0;
            o[nt][2] *= c1; o[nt][3] *= c1;
        }

        // stage P (logical [row][key] layout; output cols unaffected by k-perm)
#pragma unroll
        for (int nt = 0; nt < 4; nt++) {
            *(float2*)&Ps[row0 * PPAD + nt * 8 + tig * 2]       = make_float2(s[nt][0], s[nt][1]);
            *(float2*)&Ps[(row0 + 8) * PPAD + nt * 8 + tig * 2] = make_float2(s[nt][2], s[nt][3]);
        }
        __syncwarp();

        // O += P V with permuted-k mapping: P a-frags LDS.64; V rows 2tig,2tig+1
#pragma unroll
        for (int ks = 0; ks < 4; ks++) {
            const int kc = ks * 8;
            float2 p0 = *(const float2*)&Ps[row0 * PPAD + kc + 2 * tig];
            float2 p1 = *(const float2*)&Ps[(row0 + 8) * PPAD + kc + 2 * tig];
            uint32_t a0 = f2tf32(p0.x), a2 = f2tf32(p0.y);
            uint32_t a1 = f2tf32(p1.x), a3 = f2tf32(p1.y);
            const float* vr0 = Vb + (kc + 2 * tig) * VPAD;
            const float* vr1 = vr0 + VPAD;
#pragma unroll
            for (int nt = 0; nt < 16; nt++) {
                const int col = nt * 8 + gid;
                mma_tf32(o[nt], a0, a1, a2, a3,
                         __float_as_uint(vr0[col]), __float_as_uint(vr1[col]));
            }
        }
        __syncthreads();
    }

    // write out, pre-rounded to tf32 for the O-projection
    const float inv0 = 1.f / l0, inv1 = 1.f / l1;
    float* yp  = Y + (size_t)(b * TSEQ + q0 + row0) * CDIM + h * 128;
    float* yp8 = yp + 8 * CDIM;
#pragma unroll
    for (int nt = 0; nt < 16; nt++) {
        const int c = nt * 8 + tig * 2;
        *(float2*)&yp [c] = make_float2(rtf(o[nt][0] * inv0), rtf(o[nt][1] * inv0));
        *(float2*)&yp8[c] = make_float2(rtf(o[nt][2] * inv1), rtf(o[nt][3] * inv1));
    }
}

// ---------------------------------------------------------------------------
extern "C" void kernel_launch(void* const* d_in, const int* in_sizes, int n_in,
                              void* d_out, int out_size)
{
    const float* x   = (const float*)d_in[0];
    const float* Wq  = (const float*)d_in[1];
    const float* Wkv = (const float*)d_in[2];
    const float* Wo  = (const float*)d_in[3];
    float* out = (float*)d_out;

    float *pQ, *pKV, *pY, *pX, *pWq, *pWkv, *pWo;
    cudaGetSymbolAddress((void**)&pQ,   g_Q);
    cudaGetSymbolAddress((void**)&pKV,  g_KV);
    cudaGetSymbolAddress((void**)&pY,   g_Y);
    cudaGetSymbolAddress((void**)&pX,   g_X);
    cudaGetSymbolAddress((void**)&pWq,  g_Wq);
    cudaGetSymbolAddress((void**)&pWkv, g_Wkv);
    cudaGetSymbolAddress((void**)&pWo,  g_Wo);

    const int gemm_smem = 4 * TILEF * sizeof(float);   // 81920
    cudaFuncSetAttribute(gemm_tf32_nt, cudaFuncAttributeMaxDynamicSharedMemorySize, gemm_smem);
    cudaFuncSetAttribute(attn_mma_kernel, cudaFuncAttributeMaxDynamicSharedMemorySize, ATTN_SMEM);

    // 0) pre-round inputs to tf32
    {
        int n;
        n = MROWS * CDIM / 4;  round_tf32_kernel<<<(n + 255) / 256, 256>>>(x,   pX,   n);
        n = CDIM * CDIM / 4;   round_tf32_kernel<<<(n + 255) / 256, 256>>>(Wq,  pWq,  n);
        n = KVW * CDIM / 4;    round_tf32_kernel<<<(n + 255) / 256, 256>>>(Wkv, pWkv, n);
        n = CDIM * CDIM / 4;   round_tf32_kernel<<<(n + 255) / 256, 256>>>(Wo,  pWo,  n);
    }

    // 1) Q = x @ Wq^T  (unrounded output; attention rounds q*scale itself)
    gemm_tf32_nt<<<dim3(CDIM / 128, MROWS / 128), 256, gemm_smem>>>(pX, pWq, pQ, MROWS, CDIM, CDIM, 0);
    // 2) KV = x @ Wkv^T (rounded output: V consumed raw by attention mma)
    gemm_tf32_nt<<<dim3(KVW / 128, MROWS / 128), 256, gemm_smem>>>(pX, pWkv, pKV, MROWS, KVW, CDIM, 1);

    // 3) RoPE (writes tf32-rounded Q and K)
    {
        int totQ = MROWS * NH * 64;
        rope_kernel<<<(totQ + 255) / 256, 256>>>(pQ, MROWS, NH, CDIM);
        int totK = MROWS * NKV * 64;
        rope_kernel<<<(totK + 255) / 256, 256>>>(pKV, MROWS, NKV, KVW);
    }

    // 4) tensor-core causal flash attention (writes tf32-rounded Y)
    attn_mma_kernel<<<dim3(TSEQ / 64, NH, NB), 128, ATTN_SMEM>>>(pQ, pKV, pY);

    // 5) out = Y @ Wo^T (unrounded fp32 output)
    gemm_tf32_nt<<<dim3(CDIM / 128, MROWS / 128), 256, gemm_smem>>>(pY, pWo, out, MROWS, CDIM, CDIM, 0);
}

// round 8
// speedup vs baseline: 1.8172x; 1.8172x over previous
#include <cuda_runtime.h>
#include <cuda_fp16.h>
#include <math.h>
#include <stdint.h>

// Problem constants
#define NB    2
#define TSEQ  2048
#define CDIM  2048
#define NH    16
#define NKV   4
#define HD    128
#define MROWS (NB * TSEQ)          // 4096
#define KVW   (2 * NKV * HD)       // 1024

// Scratch (no cudaMalloc allowed)
__device__ float  g_Q[(size_t)MROWS * CDIM];
__device__ float  g_KV[(size_t)MROWS * KVW];
__device__ __half g_Yh[(size_t)MROWS * CDIM];
// fp16 copies of GEMM inputs
__device__ __half g_Xh[(size_t)MROWS * CDIM];
__device__ __half g_Wqh[(size_t)CDIM * CDIM];
__device__ __half g_Wkvh[(size_t)KVW * CDIM];
__device__ __half g_Woh[(size_t)CDIM * CDIM];

// ---------------------------------------------------------------------------
// Helpers
// ---------------------------------------------------------------------------
__device__ __forceinline__ uint32_t f2tf32(float x) {
    uint32_t r;
    asm("cvt.rna.tf32.f32 %0, %1;\n" : "=r"(r) : "f"(x));
    return r;
}

__device__ __forceinline__ void mma_tf32(float* c,
                                         uint32_t a0, uint32_t a1, uint32_t a2, uint32_t a3,
                                         uint32_t b0, uint32_t b1) {
    asm("mma.sync.aligned.m16n8k8.row.col.f32.tf32.tf32.f32 "
        "{%0,%1,%2,%3}, {%4,%5,%6,%7}, {%8,%9}, {%0,%1,%2,%3};\n"
        : "+f"(c[0]), "+f"(c[1]), "+f"(c[2]), "+f"(c[3])
        : "r"(a0), "r"(a1), "r"(a2), "r"(a3), "r"(b0), "r"(b1));
}

__device__ __forceinline__ void mma_f16(float* c,
                                        uint32_t a0, uint32_t a1, uint32_t a2, uint32_t a3,
                                        uint32_t b0, uint32_t b1) {
    asm("mma.sync.aligned.m16n8k16.row.col.f32.f16.f16.f32 "
        "{%0,%1,%2,%3}, {%4,%5,%6,%7}, {%8,%9}, {%0,%1,%2,%3};\n"
        : "+f"(c[0]), "+f"(c[1]), "+f"(c[2]), "+f"(c[3])
        : "r"(a0), "r"(a1), "r"(a2), "r"(a3), "r"(b0), "r"(b1));
}

__device__ __forceinline__ void cp_async16(uint32_t smem_addr, const void* gptr) {
    asm volatile("cp.async.cg.shared.global [%0], [%1], 16;\n"
                 :: "r"(smem_addr), "l"(gptr));
}

// ---------------------------------------------------------------------------
// fp32 -> fp16 conversion (vectorized)
// ---------------------------------------------------------------------------
__global__ void f32_to_f16_kernel(const float* __restrict__ in, __half* __restrict__ out, int n4)
{
    int i = blockIdx.x * blockDim.x + threadIdx.x;
    if (i >= n4) return;
    float4 v = ((const float4*)in)[i];
    ((__half2*)out)[2 * i]     = __floats2half2_rn(v.x, v.y);
    ((__half2*)out)[2 * i + 1] = __floats2half2_rn(v.z, v.w);
}

// ---------------------------------------------------------------------------
// FP16 tensor-core NT GEMM: C[M,N] = A[M,K] * B[N,K]^T (fp32 accumulate).
// 128x128 tile, BK=32 halfs, 256 threads (8 warps 2x4), warp tile 64x32,
// mma.sync.m16n8k16. PADH=40 halfs -> conflict-free .32 fragment loads
// (word addr = gid*20 + tig, distinct mod 32).
// ---------------------------------------------------------------------------
#define BKH   32
#define PADH  40
#define TILEH (128 * PADH)          // halfs per tile (5120)

__global__ __launch_bounds__(256, 2) void gemm_f16_nt(
    const __half* __restrict__ A, const __half* __restrict__ B,
    float* __restrict__ C, int M, int N, int K)
{
    extern __shared__ __half smh[];
    __half* Abuf[2] = { smh,              smh + TILEH };
    __half* Bbuf[2] = { smh + 2 * TILEH,  smh + 3 * TILEH };

    const int tid  = threadIdx.x;
    const int bm   = blockIdx.y * 128;
    const int bn   = blockIdx.x * 128;
    const int warp = tid >> 5;
    const int lane = tid & 31;
    const int wm   = warp >> 2;        // 0..1
    const int wn   = warp & 3;         // 0..3
    const int gid  = lane >> 2;        // 0..7
    const int tig  = lane & 3;         // 0..3

    // copy: each thread moves 32B (2x16B) of one row per tile
    const int crow = tid >> 1;         // 0..127
    const int cq   = tid & 1;          // 0..1
    const __half* gA = A + (size_t)(bm + crow) * K + cq * 16;
    const __half* gB = B + (size_t)(bn + crow) * K + cq * 16;
    const int soff = crow * PADH + cq * 16;   // halfs

    float acc[4][4][4];
#pragma unroll
    for (int mt = 0; mt < 4; mt++)
#pragma unroll
        for (int nt = 0; nt < 4; nt++)
#pragma unroll
            for (int i = 0; i < 4; i++) acc[mt][nt][i] = 0.f;

    const int niter = K / BKH;

    {
        uint32_t sa = (uint32_t)__cvta_generic_to_shared(Abuf[0] + soff);
        uint32_t sb = (uint32_t)__cvta_generic_to_shared(Bbuf[0] + soff);
#pragma unroll
        for (int j = 0; j < 2; j++) {
            cp_async16(sa + j * 16, gA + j * 8);
            cp_async16(sb + j * 16, gB + j * 8);
        }
        asm volatile("cp.async.commit_group;\n" ::: "memory");
    }

    for (int k0 = 0; k0 < niter; k0++) {
        const int buf = k0 & 1;
        if (k0 + 1 < niter) {
            const int koff = (k0 + 1) * BKH;
            uint32_t sa = (uint32_t)__cvta_generic_to_shared(Abuf[buf ^ 1] + soff);
            uint32_t sb = (uint32_t)__cvta_generic_to_shared(Bbuf[buf ^ 1] + soff);
#pragma unroll
            for (int j = 0; j < 2; j++) {
                cp_async16(sa + j * 16, gA + koff + j * 8);
                cp_async16(sb + j * 16, gB + koff + j * 8);
            }
        }
        asm volatile("cp.async.commit_group;\n" ::: "memory");
        asm volatile("cp.async.wait_group 1;\n" ::: "memory");
        __syncthreads();

        const __half* As = Abuf[buf];
        const __half* Bs = Bbuf[buf];
#pragma unroll
        for (int ks = 0; ks < 2; ks++) {
            const int kc = ks * 16;
            uint32_t af[4][4], bf[4][2];
#pragma unroll
            for (int mt = 0; mt < 4; mt++) {
                const int r = wm * 64 + mt * 16 + gid;
                af[mt][0] = *(const uint32_t*)&As[r * PADH + kc + 2 * tig];
                af[mt][1] = *(const uint32_t*)&As[(r + 8) * PADH + kc + 2 * tig];
                af[mt][2] = *(const uint32_t*)&As[r * PADH + kc + 8 + 2 * tig];
                af[mt][3] = *(const uint32_t*)&As[(r + 8) * PADH + kc + 8 + 2 * tig];
            }
#pragma unroll
            for (int nt = 0; nt < 4; nt++) {
                const int r = wn * 32 + nt * 8 + gid;
                bf[nt][0] = *(const uint32_t*)&Bs[r * PADH + kc + 2 * tig];
                bf[nt][1] = *(const uint32_t*)&Bs[r * PADH + kc + 8 + 2 * tig];
            }
#pragma unroll
            for (int mt = 0; mt < 4; mt++)
#pragma unroll
                for (int nt = 0; nt < 4; nt++)
                    mma_f16(acc[mt][nt], af[mt][0], af[mt][1], af[mt][2], af[mt][3],
                            bf[nt][0], bf[nt][1]);
        }
        __syncthreads();
    }

#pragma unroll
    for (int mt = 0; mt < 4; mt++) {
        const int r0 = bm + wm * 64 + mt * 16 + gid;
#pragma unroll
        for (int nt = 0; nt < 4; nt++) {
            const int c0 = bn + wn * 32 + nt * 8 + tig * 2;
            *(float2*)&C[(size_t)r0 * N + c0]       = make_float2(acc[mt][nt][0], acc[mt][nt][1]);
            *(float2*)&C[(size_t)(r0 + 8) * N + c0] = make_float2(acc[mt][nt][2], acc[mt][nt][3]);
        }
    }
}

// ---------------------------------------------------------------------------
// RoPE: in-place fp32, layout [rows, nheads, 128], given row stride (floats).
// ---------------------------------------------------------------------------
__global__ void rope_kernel(float* __restrict__ X, int rows, int nheads, int rowstride)
{
    int idx = blockIdx.x * blockDim.x + threadIdx.x;
    int total = rows * nheads * 64;
    if (idx >= total) return;
    int i   = idx & 63;
    int h   = (idx >> 6) % nheads;
    int row = idx / (64 * nheads);
    int t   = row & (TSEQ - 1);

    float freq = expf(-(float)i * (9.210340371976184f / 64.0f));
    float ang = (float)t * freq;
    float s, c;
    sincosf(ang, &s, &c);

    float* p = X + (size_t)row * rowstride + h * 128;
    float x0 = p[i];
    float x1 = p[i + 64];
    p[i]      = x0 * c - x1 * s;
    p[i + 64] = x1 * c + x0 * s;
}

// ---------------------------------------------------------------------------
// Tensor-core causal flash attention (tf32 mma.sync, fp32 softmax) — R6 body.
// Output Y written as fp16 for the O-projection GEMM.
// ---------------------------------------------------------------------------
#define KPAD  132
#define VPAD  136
#define PPAD  36
#define KTILE (32 * KPAD)
#define VTILE (32 * VPAD)
#define BUFSZ (KTILE + VTILE)
#define ATTN_SMEM ((2 * BUFSZ + 64 * PPAD) * 4)   // 77824 bytes

__global__ __launch_bounds__(128, 2) void attn_mma_kernel(
    const float* __restrict__ Q, const float* __restrict__ KV,
    __half* __restrict__ Y)
{
    extern __shared__ float sm[];
    float* Ps = sm + 2 * BUFSZ;

    const int b   = blockIdx.z;
    const int h   = blockIdx.y;
    const int q0  = blockIdx.x * 64;
    const int kvh = h >> 2;
    const int tid  = threadIdx.x;
    const int warp = tid >> 5;
    const int lane = tid & 31;
    const int gid  = lane >> 2;
    const int tig  = lane & 3;

    const float scale = 0.08838834764831845f;   // 1/sqrt(128)

    uint32_t qf[16][4];
    {
        const float* qp  = Q + (size_t)(b * TSEQ + q0 + warp * 16 + gid) * CDIM + h * 128;
        const float* qp8 = qp + 8 * CDIM;
#pragma unroll
        for (int ks = 0; ks < 16; ks++) {
            qf[ks][0] = f2tf32(qp [ks * 8 + tig]     * scale);
            qf[ks][1] = f2tf32(qp8[ks * 8 + tig]     * scale);
            qf[ks][2] = f2tf32(qp [ks * 8 + tig + 4] * scale);
            qf[ks][3] = f2tf32(qp8[ks * 8 + tig + 4] * scale);
        }
    }

    float o[16][4];
#pragma unroll
    for (int nt = 0; nt < 16; nt++)
#pragma unroll
        for (int i = 0; i < 4; i++) o[nt][i] = 0.f;
    float m0 = -1e30f, m1 = -1e30f, l0 = 0.f, l1 = 0.f;

    const int nkt = q0 / 32 + 2;

    {
        float* Kb = sm;
        float* Vb = sm + KTILE;
#pragma unroll
        for (int i = 0; i < 8; i++) {
            int idx = tid + i * 128;
            int r = idx >> 5, c4 = idx & 31;
            const float* src = KV + (size_t)(b * TSEQ + r) * KVW + kvh * 128 + c4 * 4;
            cp_async16((uint32_t)__cvta_generic_to_shared(Kb + r * KPAD + c4 * 4), src);
            cp_async16((uint32_t)__cvta_generic_to_shared(Vb + r * VPAD + c4 * 4), src + NKV * HD);
        }
        asm volatile("cp.async.commit_group;\n" ::: "memory");
    }

    const int row0 = warp * 16 + gid;

    for (int t = 0; t < nkt; t++) {
        const int buf = t & 1;
        if (t + 1 < nkt) {
            const int s1 = (t + 1) * 32;
            float* Kb = sm + (buf ^ 1) * BUFSZ;
            float* Vb = Kb + KTILE;
#pragma unroll
            for (int i = 0; i < 8; i++) {
                int idx = tid + i * 128;
                int r = idx >> 5, c4 = idx & 31;
                const float* src = KV + (size_t)(b * TSEQ + s1 + r) * KVW + kvh * 128 + c4 * 4;
                cp_async16((uint32_t)__cvta_generic_to_shared(Kb + r * KPAD + c4 * 4), src);
                cp_async16((uint32_t)__cvta_generic_to_shared(Vb + r * VPAD + c4 * 4), src + NKV * HD);
            }
        }
        asm volatile("cp.async.commit_group;\n" ::: "memory");
        asm volatile("cp.async.wait_group 1;\n" ::: "memory");
        __syncthreads();

        const float* Kb = sm + buf * BUFSZ;
        const float* Vb = Kb + KTILE;
        const int s0 = t * 32;

        float s[4][4];
#pragma unroll
        for (int nt = 0; nt < 4; nt++)
#pragma unroll
            for (int i = 0; i < 4; i++) s[nt][i] = 0.f;

#pragma unroll
        for (int ks = 0; ks < 16; ks++) {
            const int kc = ks * 8;
#pragma unroll
            for (int nt = 0; nt < 4; nt++) {
                const float* kr = Kb + (nt * 8 + gid) * KPAD + kc + tig;
                uint32_t b0 = f2tf32(kr[0]);
                uint32_t b1 = f2tf32(kr[4]);
                mma_tf32(s[nt], qf[ks][0], qf[ks][1], qf[ks][2], qf[ks][3], b0, b1);
            }
        }

        if (t >= nkt - 2) {
            const int r0g = q0 + row0;
#pragma unroll
            for (int nt = 0; nt < 4; nt++) {
                const int c = s0 + nt * 8 + tig * 2;
                if (c > r0g)         s[nt][0] = -1e30f;
                if (c + 1 > r0g)     s[nt][1] = -1e30f;
                if (c > r0g + 8)     s[nt][2] = -1e30f;
                if (c + 1 > r0g + 8) s[nt][3] = -1e30f;
            }
        }

        float rm0 = s[0][0], rm1 = s[0][2];
#pragma unroll
        for (int nt = 0; nt < 4; nt++) {
            rm0 = fmaxf(rm0, fmaxf(s[nt][0], s[nt][1]));
            rm1 = fmaxf(rm1, fmaxf(s[nt][2], s[nt][3]));
        }
        rm0 = fmaxf(rm0, __shfl_xor_sync(0xffffffffu, rm0, 1));
        rm0 = fmaxf(rm0, __shfl_xor_sync(0xffffffffu, rm0, 2));
        rm1 = fmaxf(rm1, __shfl_xor_sync(0xffffffffu, rm1, 1));
        rm1 = fmaxf(rm1, __shfl_xor_sync(0xffffffffu, rm1, 2));

        float mt0 = fmaxf(m0, rm0), mt1 = fmaxf(m1, rm1);
        float c0 = __expf(m0 - mt0), c1 = __expf(m1 - mt1);
        m0 = mt0; m1 = mt1;

        float rs0 = 0.f, rs1 = 0.f;
#pragma unroll
        for (int nt = 0; nt < 4; nt++) {
            s[nt][0] = __expf(s[nt][0] - m0); rs0 += s[nt][0];
            s[nt][1] = __expf(s[nt][1] - m0); rs0 += s[nt][1];
            s[nt][2] = __expf(s[nt][2] - m1); rs1 += s[nt][2];
            s[nt][3] = __expf(s[nt][3] - m1); rs1 += s[nt][3];
        }
        rs0 += __shfl_xor_sync(0xffffffffu, rs0, 1);
        rs0 += __shfl_xor_sync(0xffffffffu, rs0, 2);
        rs1 += __shfl_xor_sync(0xffffffffu, rs1, 1);
        rs1 += __shfl_xor_sync(0xffffffffu, rs1, 2);
        l0 = l0 * c0 + rs0;
        l1 = l1 * c1 + rs1;

#pragma unroll
        for (int nt = 0; nt < 16; nt++) {
            o[nt][0] *= c0; o[nt][1] *= c0;
            o[nt][2] *= c1; o[nt][3] *= c1;
        }

#pragma unroll
        for (int nt = 0; nt < 4; nt++) {
            *(float2*)&Ps[row0 * PPAD + nt * 8 + tig * 2]       = make_float2(s[nt][0], s[nt][1]);
            *(float2*)&Ps[(row0 + 8) * PPAD + nt * 8 + tig * 2] = make_float2(s[nt][2], s[nt][3]);
        }
        __syncwarp();

#pragma unroll
        for (int ks = 0; ks < 4; ks++) {
            const int kc = ks * 8;
            uint32_t a0 = f2tf32(Ps[row0 * PPAD + kc + tig]);
            uint32_t a1 = f2tf32(Ps[(row0 + 8) * PPAD + kc + tig]);
            uint32_t a2 = f2tf32(Ps[row0 * PPAD + kc + tig + 4]);
            uint32_t a3 = f2tf32(Ps[(row0 + 8) * PPAD + kc + tig + 4]);
#pragma unroll
            for (int nt = 0; nt < 16; nt++) {
                uint32_t b0 = f2tf32(Vb[(kc + tig) * VPAD + nt * 8 + gid]);
                uint32_t b1 = f2tf32(Vb[(kc + tig + 4) * VPAD + nt * 8 + gid]);
                mma_tf32(o[nt], a0, a1, a2, a3, b0, b1);
            }
        }
        __syncthreads();
    }

    // write out as fp16 (input to O-projection)
    const float inv0 = 1.f / l0, inv1 = 1.f / l1;
    __half* yp  = Y + (size_t)(b * TSEQ + q0 + row0) * CDIM + h * 128;
    __half* yp8 = yp + 8 * CDIM;
#pragma unroll
    for (int nt = 0; nt < 16; nt++) {
        const int c = nt * 8 + tig * 2;
        *(__half2*)&yp [c] = __floats2half2_rn(o[nt][0] * inv0, o[nt][1] * inv0);
        *(__half2*)&yp8[c] = __floats2half2_rn(o[nt][2] * inv1, o[nt][3] * inv1);
    }
}

// ---------------------------------------------------------------------------
extern "C" void kernel_launch(void* const* d_in, const int* in_sizes, int n_in,
                              void* d_out, int out_size)
{
    const float* x   = (const float*)d_in[0];
    const float* Wq  = (const float*)d_in[1];
    const float* Wkv = (const float*)d_in[2];
    const float* Wo  = (const float*)d_in[3];
    float* out = (float*)d_out;

    float *pQ, *pKV;
    __half *pYh, *pXh, *pWqh, *pWkvh, *pWoh;
    cudaGetSymbolAddress((void**)&pQ,    g_Q);
    cudaGetSymbolAddress((void**)&pKV,   g_KV);
    cudaGetSymbolAddress((void**)&pYh,   g_Yh);
    cudaGetSymbolAddress((void**)&pXh,   g_Xh);
    cudaGetSymbolAddress((void**)&pWqh,  g_Wqh);
    cudaGetSymbolAddress((void**)&pWkvh, g_Wkvh);
    cudaGetSymbolAddress((void**)&pWoh,  g_Woh);

    const int gemm_smem = 4 * TILEH * sizeof(__half);   // 40960
    cudaFuncSetAttribute(gemm_f16_nt, cudaFuncAttributeMaxDynamicSharedMemorySize, gemm_smem);
    cudaFuncSetAttribute(attn_mma_kernel, cudaFuncAttributeMaxDynamicSharedMemorySize, ATTN_SMEM);

    // 0) convert GEMM inputs to fp16
    {
        int n;
        n = MROWS * CDIM / 4;  f32_to_f16_kernel<<<(n + 255) / 256, 256>>>(x,   pXh,   n);
        n = CDIM * CDIM / 4;   f32_to_f16_kernel<<<(n + 255) / 256, 256>>>(Wq,  pWqh,  n);
        n = KVW * CDIM / 4;    f32_to_f16_kernel<<<(n + 255) / 256, 256>>>(Wkv, pWkvh, n);
        n = CDIM * CDIM / 4;   f32_to_f16_kernel<<<(n + 255) / 256, 256>>>(Wo,  pWoh,  n);
    }

    // 1) Q = x @ Wq^T  (fp16 in, fp32 out)
    gemm_f16_nt<<<dim3(CDIM / 128, MROWS / 128), 256, gemm_smem>>>(pXh, pWqh, pQ, MROWS, CDIM, CDIM);
    // 2) KV = x @ Wkv^T
    gemm_f16_nt<<<dim3(KVW / 128, MROWS / 128), 256, gemm_smem>>>(pXh, pWkvh, pKV, MROWS, KVW, CDIM);

    // 3) RoPE (fp32 in place)
    {
        int totQ = MROWS * NH * 64;
        rope_kernel<<<(totQ + 255) / 256, 256>>>(pQ, MROWS, NH, CDIM);
        int totK = MROWS * NKV * 64;
        rope_kernel<<<(totK + 255) / 256, 256>>>(pKV, MROWS, NKV, KVW);
    }

    // 4) tensor-core causal flash attention (fp32 in, fp16 Y out)
    attn_mma_kernel<<<dim3(TSEQ / 64, NH, NB), 128, ATTN_SMEM>>>(pQ, pKV, pYh);

    // 5) out = Y @ Wo^T (fp16 in, fp32 out)
    gemm_f16_nt<<<dim3(CDIM / 128, MROWS / 128), 256, gemm_smem>>>(pYh, pWoh, out, MROWS, CDIM, CDIM);
}

// round 9
// speedup vs baseline: 2.2696x; 1.2490x over previous
#include <cuda_runtime.h>
#include <cuda_fp16.h>
#include <math.h>
#include <stdint.h>

// Problem constants
#define NB    2
#define TSEQ  2048
#define CDIM  2048
#define NH    16
#define NKV   4
#define HD    128
#define MROWS (NB * TSEQ)          // 4096
#define KVW   (2 * NKV * HD)       // 1024
#define KVHW  (NKV * HD)           // 512

// Scratch (no cudaMalloc allowed)
__device__ float  g_Q[(size_t)MROWS * CDIM];      // fp32 Q (pre-rope)
__device__ float  g_KV[(size_t)MROWS * KVW];      // fp32 KV (pre-rope)
__device__ __half g_Qh[(size_t)MROWS * CDIM];     // fp16 roped+scaled Q
__device__ __half g_Kh[(size_t)MROWS * KVHW];     // fp16 roped K  [b*t][kv*128]
__device__ __half g_Vth[(size_t)NB * NKV * HD * TSEQ]; // fp16 V^T [b,kv,d][t]
__device__ __half g_Yh[(size_t)MROWS * CDIM];
// fp16 copies of GEMM inputs
__device__ __half g_Xh[(size_t)MROWS * CDIM];
__device__ __half g_Wqh[(size_t)CDIM * CDIM];
__device__ __half g_Wkvh[(size_t)KVW * CDIM];
__device__ __half g_Woh[(size_t)CDIM * CDIM];

// ---------------------------------------------------------------------------
// Helpers
// ---------------------------------------------------------------------------
__device__ __forceinline__ void mma_f16(float* c,
                                        uint32_t a0, uint32_t a1, uint32_t a2, uint32_t a3,
                                        uint32_t b0, uint32_t b1) {
    asm("mma.sync.aligned.m16n8k16.row.col.f32.f16.f16.f32 "
        "{%0,%1,%2,%3}, {%4,%5,%6,%7}, {%8,%9}, {%0,%1,%2,%3};\n"
        : "+f"(c[0]), "+f"(c[1]), "+f"(c[2]), "+f"(c[3])
        : "r"(a0), "r"(a1), "r"(a2), "r"(a3), "r"(b0), "r"(b1));
}

__device__ __forceinline__ void cp_async16(uint32_t smem_addr, const void* gptr) {
    asm volatile("cp.async.cg.shared.global [%0], [%1], 16;\n"
                 :: "r"(smem_addr), "l"(gptr));
}

// ---------------------------------------------------------------------------
// fp32 -> fp16 conversion (vectorized)
// ---------------------------------------------------------------------------
__global__ void f32_to_f16_kernel(const float* __restrict__ in, __half* __restrict__ out, int n4)
{
    int i = blockIdx.x * blockDim.x + threadIdx.x;
    if (i >= n4) return;
    float4 v = ((const float4*)in)[i];
    ((__half2*)out)[2 * i]     = __floats2half2_rn(v.x, v.y);
    ((__half2*)out)[2 * i + 1] = __floats2half2_rn(v.z, v.w);
}

// ---------------------------------------------------------------------------
// FP16 tensor-core NT GEMM: C[M,N] = A[M,K] * B[N,K]^T (fp32 accumulate).
// (unchanged from R8)
// ---------------------------------------------------------------------------
#define BKH   32
#define PADH  40
#define TILEH (128 * PADH)

__global__ __launch_bounds__(256, 2) void gemm_f16_nt(
    const __half* __restrict__ A, const __half* __restrict__ B,
    float* __restrict__ C, int M, int N, int K)
{
    extern __shared__ __half smh[];
    __half* Abuf[2] = { smh,              smh + TILEH };
    __half* Bbuf[2] = { smh + 2 * TILEH,  smh + 3 * TILEH };

    const int tid  = threadIdx.x;
    const int bm   = blockIdx.y * 128;
    const int bn   = blockIdx.x * 128;
    const int warp = tid >> 5;
    const int lane = tid & 31;
    const int wm   = warp >> 2;
    const int wn   = warp & 3;
    const int gid  = lane >> 2;
    const int tig  = lane & 3;

    const int crow = tid >> 1;
    const int cq   = tid & 1;
    const __half* gA = A + (size_t)(bm + crow) * K + cq * 16;
    const __half* gB = B + (size_t)(bn + crow) * K + cq * 16;
    const int soff = crow * PADH + cq * 16;

    float acc[4][4][4];
#pragma unroll
    for (int mt = 0; mt < 4; mt++)
#pragma unroll
        for (int nt = 0; nt < 4; nt++)
#pragma unroll
            for (int i = 0; i < 4; i++) acc[mt][nt][i] = 0.f;

    const int niter = K / BKH;

    {
        uint32_t sa = (uint32_t)__cvta_generic_to_shared(Abuf[0] + soff);
        uint32_t sb = (uint32_t)__cvta_generic_to_shared(Bbuf[0] + soff);
#pragma unroll
        for (int j = 0; j < 2; j++) {
            cp_async16(sa + j * 16, gA + j * 8);
            cp_async16(sb + j * 16, gB + j * 8);
        }
        asm volatile("cp.async.commit_group;\n" ::: "memory");
    }

    for (int k0 = 0; k0 < niter; k0++) {
        const int buf = k0 & 1;
        if (k0 + 1 < niter) {
            const int koff = (k0 + 1) * BKH;
            uint32_t sa = (uint32_t)__cvta_generic_to_shared(Abuf[buf ^ 1] + soff);
            uint32_t sb = (uint32_t)__cvta_generic_to_shared(Bbuf[buf ^ 1] + soff);
#pragma unroll
            for (int j = 0; j < 2; j++) {
                cp_async16(sa + j * 16, gA + koff + j * 8);
                cp_async16(sb + j * 16, gB + koff + j * 8);
            }
        }
        asm volatile("cp.async.commit_group;\n" ::: "memory");
        asm volatile("cp.async.wait_group 1;\n" ::: "memory");
        __syncthreads();

        const __half* As = Abuf[buf];
        const __half* Bs = Bbuf[buf];
#pragma unroll
        for (int ks = 0; ks < 2; ks++) {
            const int kc = ks * 16;
            uint32_t af[4][4], bf[4][2];
#pragma unroll
            for (int mt = 0; mt < 4; mt++) {
                const int r = wm * 64 + mt * 16 + gid;
                af[mt][0] = *(const uint32_t*)&As[r * PADH + kc + 2 * tig];
                af[mt][1] = *(const uint32_t*)&As[(r + 8) * PADH + kc + 2 * tig];
                af[mt][2] = *(const uint32_t*)&As[r * PADH + kc + 8 + 2 * tig];
                af[mt][3] = *(const uint32_t*)&As[(r + 8) * PADH + kc + 8 + 2 * tig];
            }
#pragma unroll
            for (int nt = 0; nt < 4; nt++) {
                const int r = wn * 32 + nt * 8 + gid;
                bf[nt][0] = *(const uint32_t*)&Bs[r * PADH + kc + 2 * tig];
                bf[nt][1] = *(const uint32_t*)&Bs[r * PADH + kc + 8 + 2 * tig];
            }
#pragma unroll
            for (int mt = 0; mt < 4; mt++)
#pragma unroll
                for (int nt = 0; nt < 4; nt++)
                    mma_f16(acc[mt][nt], af[mt][0], af[mt][1], af[mt][2], af[mt][3],
                            bf[nt][0], bf[nt][1]);
        }
        __syncthreads();
    }

#pragma unroll
    for (int mt = 0; mt < 4; mt++) {
        const int r0 = bm + wm * 64 + mt * 16 + gid;
#pragma unroll
        for (int nt = 0; nt < 4; nt++) {
            const int c0 = bn + wn * 32 + nt * 8 + tig * 2;
            *(float2*)&C[(size_t)r0 * N + c0]       = make_float2(acc[mt][nt][0], acc[mt][nt][1]);
            *(float2*)&C[(size_t)(r0 + 8) * N + c0] = make_float2(acc[mt][nt][2], acc[mt][nt][3]);
        }
    }
}

// ---------------------------------------------------------------------------
// RoPE -> fp16 emit.
// rope_q_half: reads fp32 Q [b*t][H*128], rotates, scales by 1/sqrt(D),
//              writes fp16 to Qh (same layout).
// rope_k_half: reads fp32 K part of KV [b*t][kv*128], rotates,
//              writes fp16 Kh [b*t][kv*128].
// ---------------------------------------------------------------------------
__global__ void rope_q_half(const float* __restrict__ X, __half* __restrict__ O)
{
    int idx = blockIdx.x * blockDim.x + threadIdx.x;
    if (idx >= MROWS * NH * 64) return;
    int i   = idx & 63;
    int h   = (idx >> 6) % NH;
    int row = idx / (64 * NH);
    int t   = row & (TSEQ - 1);

    float freq = expf(-(float)i * (9.210340371976184f / 64.0f));
    float ang = (float)t * freq;
    float s, c;
    sincosf(ang, &s, &c);

    const float scale = 0.08838834764831845f;
    const float* p = X + (size_t)row * CDIM + h * 128;
    __half* o = O + (size_t)row * CDIM + h * 128;
    float x0 = p[i], x1 = p[i + 64];
    o[i]      = __float2half((x0 * c - x1 * s) * scale);
    o[i + 64] = __float2half((x1 * c + x0 * s) * scale);
}

__global__ void rope_k_half(const float* __restrict__ KV, __half* __restrict__ O)
{
    int idx = blockIdx.x * blockDim.x + threadIdx.x;
    if (idx >= MROWS * NKV * 64) return;
    int i   = idx & 63;
    int h   = (idx >> 6) % NKV;
    int row = idx / (64 * NKV);
    int t   = row & (TSEQ - 1);

    float freq = expf(-(float)i * (9.210340371976184f / 64.0f));
    float ang = (float)t * freq;
    float s, c;
    sincosf(ang, &s, &c);

    const float* p = KV + (size_t)row * KVW + h * 128;
    __half* o = O + (size_t)row * KVHW + h * 128;
    float x0 = p[i], x1 = p[i + 64];
    o[i]      = __float2half(x0 * c - x1 * s);
    o[i + 64] = __float2half(x1 * c + x0 * s);
}

// ---------------------------------------------------------------------------
// V -> fp16 transposed: Vt[(b*NKV+kv)*HD + d][TSEQ] = V[b,t,kv,d]
// block (32,8), grid (T/32, HD/32, NB*NKV); smem transpose tile.
// ---------------------------------------------------------------------------
__global__ void v_transpose_half(const float* __restrict__ KV, __half* __restrict__ Vt)
{
    __shared__ float tile[32][33];
    const int bk = blockIdx.z;
    const int b  = bk / NKV, kv = bk % NKV;
    const int t0 = blockIdx.x * 32;
    const int d0 = blockIdx.y * 32;
    const int tx = threadIdx.x, ty = threadIdx.y;

#pragma unroll
    for (int i = ty; i < 32; i += 8)
        tile[i][tx] = KV[(size_t)(b * TSEQ + t0 + i) * KVW + KVHW + kv * 128 + d0 + tx];
    __syncthreads();
#pragma unroll
    for (int i = ty; i < 32; i += 8)
        Vt[((size_t)bk * HD + d0 + i) * TSEQ + t0 + tx] = __float2half(tile[tx][i]);
}

// ---------------------------------------------------------------------------
// FP16 tensor-core causal flash attention (fp32 softmax/accum).
// Grid: (T/64, H, B), 128 threads (4 warps). Bc=32, double-buffered fp16 K/Vt.
// K tile: 32 x 136 halfs; Vt tile: 128 x 40 halfs; P: 64 x 40 halfs.
// ---------------------------------------------------------------------------
#define KPADH 136
#define VPADH 40
#define PPADH 40
#define KTILEH (32 * KPADH)       // 4352 halfs
#define VTILEH (128 * VPADH)      // 5120 halfs
#define BUFH   (KTILEH + VTILEH)  // 9472 halfs
#define ATTN_SMEM ((2 * BUFH + 64 * PPADH) * 2)   // 43008 bytes

__global__ __launch_bounds__(128, 2) void attn_f16_kernel(
    const __half* __restrict__ Qh, const __half* __restrict__ Kh,
    const __half* __restrict__ Vt, __half* __restrict__ Y)
{
    extern __shared__ __half smh[];
    __half* Ps = smh + 2 * BUFH;

    const int b   = blockIdx.z;
    const int h   = blockIdx.y;
    const int q0  = blockIdx.x * 64;
    const int kvh = h >> 2;
    const int tid  = threadIdx.x;
    const int warp = tid >> 5;
    const int lane = tid & 31;
    const int gid  = lane >> 2;
    const int tig  = lane & 3;

    // Q fragments (scale pre-folded): 8 k-steps of 16
    uint32_t qf[8][4];
    {
        const __half* qp  = Qh + (size_t)(b * TSEQ + q0 + warp * 16 + gid) * CDIM + h * 128;
        const __half* qp8 = qp + 8 * CDIM;
#pragma unroll
        for (int ks = 0; ks < 8; ks++) {
            qf[ks][0] = *(const uint32_t*)&qp [ks * 16 + 2 * tig];
            qf[ks][1] = *(const uint32_t*)&qp8[ks * 16 + 2 * tig];
            qf[ks][2] = *(const uint32_t*)&qp [ks * 16 + 8 + 2 * tig];
            qf[ks][3] = *(const uint32_t*)&qp8[ks * 16 + 8 + 2 * tig];
        }
    }

    float o[16][4];
#pragma unroll
    for (int nt = 0; nt < 16; nt++)
#pragma unroll
        for (int i = 0; i < 4; i++) o[nt][i] = 0.f;
    float m0 = -1e30f, m1 = -1e30f, l0 = 0.f, l1 = 0.f;

    const int nkt = q0 / 32 + 2;

    const __half* Kbase  = Kh + (size_t)(b * TSEQ) * KVHW + kvh * 128;
    const __half* Vtbase = Vt + ((size_t)(b * NKV + kvh) * HD) * TSEQ;

    // prologue: tile 0
    {
        __half* Kb = smh;
        __half* Vb = smh + KTILEH;
#pragma unroll
        for (int i = 0; i < 4; i++) {
            int idx = tid + i * 128;
            int kr = idx >> 4, kc = idx & 15;           // K: 32 rows x 16 chunks
            cp_async16((uint32_t)__cvta_generic_to_shared(Kb + kr * KPADH + kc * 8),
                       Kbase + (size_t)kr * KVHW + kc * 8);
            int vr = idx >> 2, vc = idx & 3;            // Vt: 128 rows x 4 chunks
            cp_async16((uint32_t)__cvta_generic_to_shared(Vb + vr * VPADH + vc * 8),
                       Vtbase + (size_t)vr * TSEQ + vc * 8);
        }
        asm volatile("cp.async.commit_group;\n" ::: "memory");
    }

    const int row0 = warp * 16 + gid;

    for (int t = 0; t < nkt; t++) {
        const int buf = t & 1;
        if (t + 1 < nkt) {
            const int s1 = (t + 1) * 32;
            __half* Kb = smh + (buf ^ 1) * BUFH;
            __half* Vb = Kb + KTILEH;
#pragma unroll
            for (int i = 0; i < 4; i++) {
                int idx = tid + i * 128;
                int kr = idx >> 4, kc = idx & 15;
                cp_async16((uint32_t)__cvta_generic_to_shared(Kb + kr * KPADH + kc * 8),
                           Kbase + (size_t)(s1 + kr) * KVHW + kc * 8);
                int vr = idx >> 2, vc = idx & 3;
                cp_async16((uint32_t)__cvta_generic_to_shared(Vb + vr * VPADH + vc * 8),
                           Vtbase + (size_t)vr * TSEQ + s1 + vc * 8);
            }
        }
        asm volatile("cp.async.commit_group;\n" ::: "memory");
        asm volatile("cp.async.wait_group 1;\n" ::: "memory");
        __syncthreads();

        const __half* Kb = smh + buf * BUFH;
        const __half* Vb = Kb + KTILEH;
        const int s0 = t * 32;

        float s[4][4];
#pragma unroll
        for (int nt = 0; nt < 4; nt++)
#pragma unroll
            for (int i = 0; i < 4; i++) s[nt][i] = 0.f;

        // S = Q K^T
#pragma unroll
        for (int ks = 0; ks < 8; ks++) {
            const int kc = ks * 16;
#pragma unroll
            for (int nt = 0; nt < 4; nt++) {
                const __half* kr = Kb + (nt * 8 + gid) * KPADH + kc + 2 * tig;
                uint32_t b0 = *(const uint32_t*)kr;
                uint32_t b1 = *(const uint32_t*)(kr + 8);
                mma_f16(s[nt], qf[ks][0], qf[ks][1], qf[ks][2], qf[ks][3], b0, b1);
            }
        }

        if (t >= nkt - 2) {
            const int r0g = q0 + row0;
#pragma unroll
            for (int nt = 0; nt < 4; nt++) {
                const int c = s0 + nt * 8 + tig * 2;
                if (c > r0g)         s[nt][0] = -1e30f;
                if (c + 1 > r0g)     s[nt][1] = -1e30f;
                if (c > r0g + 8)     s[nt][2] = -1e30f;
                if (c + 1 > r0g + 8) s[nt][3] = -1e30f;
            }
        }

        float rm0 = s[0][0], rm1 = s[0][2];
#pragma unroll
        for (int nt = 0; nt < 4; nt++) {
            rm0 = fmaxf(rm0, fmaxf(s[nt][0], s[nt][1]));
            rm1 = fmaxf(rm1, fmaxf(s[nt][2], s[nt][3]));
        }
        rm0 = fmaxf(rm0, __shfl_xor_sync(0xffffffffu, rm0, 1));
        rm0 = fmaxf(rm0, __shfl_xor_sync(0xffffffffu, rm0, 2));
        rm1 = fmaxf(rm1, __shfl_xor_sync(0xffffffffu, rm1, 1));
        rm1 = fmaxf(rm1, __shfl_xor_sync(0xffffffffu, rm1, 2));

        float mt0 = fmaxf(m0, rm0), mt1 = fmaxf(m1, rm1);
        float c0 = __expf(m0 - mt0), c1 = __expf(m1 - mt1);
        m0 = mt0; m1 = mt1;

        float rs0 = 0.f, rs1 = 0.f;
#pragma unroll
        for (int nt = 0; nt < 4; nt++) {
            s[nt][0] = __expf(s[nt][0] - m0); rs0 += s[nt][0];
            s[nt][1] = __expf(s[nt][1] - m0); rs0 += s[nt][1];
            s[nt][2] = __expf(s[nt][2] - m1); rs1 += s[nt][2];
            s[nt][3] = __expf(s[nt][3] - m1); rs1 += s[nt][3];
        }
        rs0 += __shfl_xor_sync(0xffffffffu, rs0, 1);
        rs0 += __shfl_xor_sync(0xffffffffu, rs0, 2);
        rs1 += __shfl_xor_sync(0xffffffffu, rs1, 1);
        rs1 += __shfl_xor_sync(0xffffffffu, rs1, 2);
        l0 = l0 * c0 + rs0;
        l1 = l1 * c1 + rs1;

#pragma unroll
        for (int nt = 0; nt < 16; nt++) {
            o[nt][0] *= c0; o[nt][1] *= c0;
            o[nt][2] *= c1; o[nt][3] *= c1;
        }

        // stage P as fp16 (warp-private rows)
#pragma unroll
        for (int nt = 0; nt < 4; nt++) {
            *(__half2*)&Ps[row0 * PPADH + nt * 8 + 2 * tig]       = __floats2half2_rn(s[nt][0], s[nt][1]);
            *(__half2*)&Ps[(row0 + 8) * PPADH + nt * 8 + 2 * tig] = __floats2half2_rn(s[nt][2], s[nt][3]);
        }
        __syncwarp();

        // O += P V   (V^T tile: rows = dims, cols = keys)
#pragma unroll
        for (int ks = 0; ks < 2; ks++) {
            const int kc = ks * 16;
            uint32_t a0 = *(const uint32_t*)&Ps[row0 * PPADH + kc + 2 * tig];
            uint32_t a1 = *(const uint32_t*)&Ps[(row0 + 8) * PPADH + kc + 2 * tig];
            uint32_t a2 = *(const uint32_t*)&Ps[row0 * PPADH + kc + 8 + 2 * tig];
            uint32_t a3 = *(const uint32_t*)&Ps[(row0 + 8) * PPADH + kc + 8 + 2 * tig];
#pragma unroll
            for (int nt = 0; nt < 16; nt++) {
                const __half* vr = Vb + (nt * 8 + gid) * VPADH + kc + 2 * tig;
                uint32_t b0 = *(const uint32_t*)vr;
                uint32_t b1 = *(const uint32_t*)(vr + 8);
                mma_f16(o[nt], a0, a1, a2, a3, b0, b1);
            }
        }
        __syncthreads();
    }

    // write out as fp16 (input to O-projection)
    const float inv0 = 1.f / l0, inv1 = 1.f / l1;
    __half* yp  = Y + (size_t)(b * TSEQ + q0 + row0) * CDIM + h * 128;
    __half* yp8 = yp + 8 * CDIM;
#pragma unroll
    for (int nt = 0; nt < 16; nt++) {
        const int c = nt * 8 + tig * 2;
        *(__half2*)&yp [c] = __floats2half2_rn(o[nt][0] * inv0, o[nt][1] * inv0);
        *(__half2*)&yp8[c] = __floats2half2_rn(o[nt][2] * inv1, o[nt][3] * inv1);
    }
}

// ---------------------------------------------------------------------------
extern "C" void kernel_launch(void* const* d_in, const int* in_sizes, int n_in,
                              void* d_out, int out_size)
{
    const float* x   = (const float*)d_in[0];
    const float* Wq  = (const float*)d_in[1];
    const float* Wkv = (const float*)d_in[2];
    const float* Wo  = (const float*)d_in[3];
    float* out = (float*)d_out;

    float *pQ, *pKV;
    __half *pQh, *pKh, *pVth, *pYh, *pXh, *pWqh, *pWkvh, *pWoh;
    cudaGetSymbolAddress((void**)&pQ,    g_Q);
    cudaGetSymbolAddress((void**)&pKV,   g_KV);
    cudaGetSymbolAddress((void**)&pQh,   g_Qh);
    cudaGetSymbolAddress((void**)&pKh,   g_Kh);
    cudaGetSymbolAddress((void**)&pVth,  g_Vth);
    cudaGetSymbolAddress((void**)&pYh,   g_Yh);
    cudaGetSymbolAddress((void**)&pXh,   g_Xh);
    cudaGetSymbolAddress((void**)&pWqh,  g_Wqh);
    cudaGetSymbolAddress((void**)&pWkvh, g_Wkvh);
    cudaGetSymbolAddress((void**)&pWoh,  g_Woh);

    const int gemm_smem = 4 * TILEH * sizeof(__half);   // 40960
    cudaFuncSetAttribute(gemm_f16_nt, cudaFuncAttributeMaxDynamicSharedMemorySize, gemm_smem);
    cudaFuncSetAttribute(attn_f16_kernel, cudaFuncAttributeMaxDynamicSharedMemorySize, ATTN_SMEM);

    // 0) convert GEMM inputs to fp16
    {
        int n;
        n = MROWS * CDIM / 4;  f32_to_f16_kernel<<<(n + 255) / 256, 256>>>(x,   pXh,   n);
        n = CDIM * CDIM / 4;   f32_to_f16_kernel<<<(n + 255) / 256, 256>>>(Wq,  pWqh,  n);
        n = KVW * CDIM / 4;    f32_to_f16_kernel<<<(n + 255) / 256, 256>>>(Wkv, pWkvh, n);
        n = CDIM * CDIM / 4;   f32_to_f16_kernel<<<(n + 255) / 256, 256>>>(Wo,  pWoh,  n);
    }

    // 1) Q = x @ Wq^T ; 2) KV = x @ Wkv^T  (fp16 in, fp32 out)
    gemm_f16_nt<<<dim3(CDIM / 128, MROWS / 128), 256, gemm_smem>>>(pXh, pWqh, pQ, MROWS, CDIM, CDIM);
    gemm_f16_nt<<<dim3(KVW / 128, MROWS / 128), 256, gemm_smem>>>(pXh, pWkvh, pKV, MROWS, KVW, CDIM);

    // 3) RoPE -> fp16 Q/K ; V -> fp16 transposed
    {
        int nq = MROWS * NH * 64;
        rope_q_half<<<(nq + 255) / 256, 256>>>(pQ, pQh);
        int nk = MROWS * NKV * 64;
        rope_k_half<<<(nk + 255) / 256, 256>>>(pKV, pKh);
        v_transpose_half<<<dim3(TSEQ / 32, HD / 32, NB * NKV), dim3(32, 8)>>>(pKV, pVth);
    }

    // 4) fp16 tensor-core causal flash attention (fp16 Y out)
    attn_f16_kernel<<<dim3(TSEQ / 64, NH, NB), 128, ATTN_SMEM>>>(pQh, pKh, pVth, pYh);

    // 5) out = Y @ Wo^T (fp16 in, fp32 out)
    gemm_f16_nt<<<dim3(CDIM / 128, MROWS / 128), 256, gemm_smem>>>(pYh, pWoh, out, MROWS, CDIM, CDIM);
}